// round 12
// baseline (speedup 1.0000x reference)
#include <cuda_runtime.h>
#include <cuda_bf16.h>
#include <cstdint>

#define NUM_CLASSES 1000
#define CPAD        1024                   // padded class count
#define FEAT_DIM    256
#define N_ROWS      262144
#define ALPHA       0.5f
#define HB          64                     // index blocks (all co-resident)
#define ROWS_PER_HB (N_ROWS / HB)          // 4096
#define RPT         (ROWS_PER_HB / 256)    // 16 rows per thread
#define CHUNK       512                    // rows per gather block
#define NCHUNK      (N_ROWS / CHUNK)       // 512 gather blocks

// Scratch (device globals — no allocation allowed).
__device__ int g_parthist[HB * CPAD];
__device__ int g_offsets[NUM_CLASSES];
__device__ int g_counts[NUM_CLASSES];
__device__ int g_rowidx[N_ROWS];
__device__ __align__(16) float g_sums[NUM_CLASSES * FEAT_DIM];
__device__ unsigned g_cnt1 = 0, g_gen1 = 0;

// Spin barrier among the 64 co-resident index blocks (self-resetting).
__device__ __forceinline__ void spin_barrier(unsigned* cnt, unsigned* gen, unsigned nb) {
    __syncthreads();
    if (threadIdx.x == 0) {
        __threadfence();
        unsigned g = atomicAdd(gen, 0u);
        unsigned old = atomicAdd(cnt, 1u);
        if (old == nb - 1) {
            atomicExch(cnt, 0u);
            __threadfence();
            atomicAdd(gen, 1u);
        } else {
            while (atomicAdd(gen, 0u) == g) __nanosleep(64);
        }
        __threadfence();
    }
    __syncthreads();
}

#define F4ADD(a, b) { (a).x += (b).x; (a).y += (b).y; (a).z += (b).z; (a).w += (b).w; }

__device__ __forceinline__ void red_add_v4(float* addr, float4 v) {
    asm volatile("red.global.add.v4.f32 [%0], {%1, %2, %3, %4};"
                 :: "l"(addr), "f"(v.x), "f"(v.y), "f"(v.z), "f"(v.w)
                 : "memory");
}

// ---------------------------------------------------------------------------
// K1: index build (R7-proven) + zero g_sums.
// ---------------------------------------------------------------------------
__global__ void __launch_bounds__(256)
index_kernel(const int* __restrict__ labels) {
    __shared__ int shA[CPAD];
    __shared__ int shP[CPAD];
    __shared__ int shS[256];

    int tid = threadIdx.x;
    int myB = blockIdx.x;

    // Zero the RED accumulator (1 MB spread over 64 blocks).
    {
        float4* s4 = reinterpret_cast<float4*>(g_sums);
        int total4 = NUM_CLASSES * FEAT_DIM / 4;          // 64000
        for (int i = myB * 256 + tid; i < total4; i += HB * 256)
            s4[i] = make_float4(0.f, 0.f, 0.f, 0.f);
    }

    // --- Phase A: histogram + ranks (held in registers) ---
#pragma unroll
    for (int c = tid; c < CPAD; c += 256) shA[c] = 0;
    __syncthreads();

    const int4* __restrict__ lab4 = reinterpret_cast<const int4*>(labels);
    int base4 = myB * (ROWS_PER_HB / 4);

    int lab[RPT], rnk[RPT];
#pragma unroll
    for (int k = 0; k < RPT / 4; k++) {
        int4 L = lab4[base4 + tid + k * 256];
        lab[k * 4 + 0] = L.x; lab[k * 4 + 1] = L.y;
        lab[k * 4 + 2] = L.z; lab[k * 4 + 3] = L.w;
    }
#pragma unroll
    for (int e = 0; e < RPT; e++) rnk[e] = atomicAdd(&shA[lab[e]], 1);
    __syncthreads();

#pragma unroll
    for (int c = tid; c < CPAD; c += 256)
        g_parthist[myB * CPAD + c] = shA[c];

    spin_barrier(&g_cnt1, &g_gen1, HB);

    // --- Phase B: totals + own-prefix in one sweep (L2-hot) ---
#pragma unroll 1
    for (int q = 0; q < 4; q++) {
        int c = tid + q * 256;
        int tot = 0, pre = 0;
#pragma unroll 8
        for (int b = 0; b < HB; b++) {
            int v = g_parthist[b * CPAD + c];
            tot += v;
            pre += (b < myB) ? v : 0;
        }
        shA[c] = tot;
        shP[c] = pre;
    }
    __syncthreads();

    int t4 = tid * 4;
    int s0 = shA[t4], s1 = shA[t4 + 1], s2 = shA[t4 + 2], s3 = shA[t4 + 3];
    int mysum = s0 + s1 + s2 + s3;
    shS[tid] = mysum;
    __syncthreads();
#pragma unroll
    for (int off = 1; off < 256; off <<= 1) {
        int v = (tid >= off) ? shS[tid - off] : 0;
        __syncthreads();
        shS[tid] += v;
        __syncthreads();
    }
    int e0 = shS[tid] - mysum;
    int e1 = e0 + s0, e2 = e1 + s1, e3 = e2 + s2;

    if (myB == 0) {
        if (t4 + 0 < NUM_CLASSES) { g_offsets[t4 + 0] = e0; g_counts[t4 + 0] = s0; }
        if (t4 + 1 < NUM_CLASSES) { g_offsets[t4 + 1] = e1; g_counts[t4 + 1] = s1; }
        if (t4 + 2 < NUM_CLASSES) { g_offsets[t4 + 2] = e2; g_counts[t4 + 2] = s2; }
        if (t4 + 3 < NUM_CLASSES) { g_offsets[t4 + 3] = e3; g_counts[t4 + 3] = s3; }
    }

    shA[t4 + 0] = e0 + shP[t4 + 0];
    shA[t4 + 1] = e1 + shP[t4 + 1];
    shA[t4 + 2] = e2 + shP[t4 + 2];
    shA[t4 + 3] = e3 + shP[t4 + 3];
    __syncthreads();

    int rowbase = myB * ROWS_PER_HB;
#pragma unroll
    for (int k = 0; k < RPT / 4; k++) {
#pragma unroll
        for (int e = 0; e < 4; e++) {
            int idx = k * 4 + e;
            int row = rowbase + (tid + k * 256) * 4 + e;
            g_rowidx[shA[lab[idx]] + rnk[idx]] = row;
        }
    }
}

// ---------------------------------------------------------------------------
// K2: perfectly balanced gather — each block owns CHUNK consecutive entries
// of the class-sorted rowidx. Per class segment: accumulate (R7 loop), smem
// cross-slot reduce, one v4-RED per 16B of the class sum.
// ---------------------------------------------------------------------------
__global__ void __launch_bounds__(256, 4)
chunksum_kernel(const float* __restrict__ features) {
    __shared__ float4 sred[256];
    int tid = threadIdx.x;
    int r4 = tid >> 6;   // row slot 0..3
    int c4 = tid & 63;   // float4 column 0..63
    const float4* __restrict__ f4 = reinterpret_cast<const float4*>(features);

    int s = blockIdx.x * CHUNK;
    int e = s + CHUNK;

    // Largest cls with offsets[cls] <= s  (offsets[0] == 0).
    int lo = 0, hi = NUM_CLASSES - 1;
    while (lo < hi) {
        int mid = (lo + hi + 1) >> 1;
        if (g_offsets[mid] <= s) lo = mid; else hi = mid - 1;
    }
    int cls = lo;
    int pos = s;

    while (pos < e) {
        while (cls < NUM_CLASSES - 1 && g_offsets[cls + 1] <= pos) cls++;
        int cend = g_offsets[cls] + g_counts[cls];
        int segend = min(e, cend);

        float4 a0 = make_float4(0.f, 0.f, 0.f, 0.f);
        float4 a1 = a0, a2 = a0, a3 = a0;

        int i = pos + r4;
        for (; i + 12 < segend; i += 16) {
            int i0 = g_rowidx[i];
            int i1 = g_rowidx[i + 4];
            int i2 = g_rowidx[i + 8];
            int i3 = g_rowidx[i + 12];
            float4 v0 = __ldcs(&f4[(size_t)i0 * 64 + c4]);
            float4 v1 = __ldcs(&f4[(size_t)i1 * 64 + c4]);
            float4 v2 = __ldcs(&f4[(size_t)i2 * 64 + c4]);
            float4 v3 = __ldcs(&f4[(size_t)i3 * 64 + c4]);
            F4ADD(a0, v0); F4ADD(a1, v1); F4ADD(a2, v2); F4ADD(a3, v3);
        }
        for (; i < segend; i += 4) {
            float4 v = __ldcs(&f4[(size_t)g_rowidx[i] * 64 + c4]);
            F4ADD(a0, v);
        }
        F4ADD(a0, a1); F4ADD(a2, a3); F4ADD(a0, a2);

        sred[tid] = a0;
        __syncthreads();
        if (tid < 64) {
            float4 t0 = sred[tid];
            float4 t1 = sred[tid + 64];
            float4 t2 = sred[tid + 128];
            float4 t3 = sred[tid + 192];
            F4ADD(t0, t1); F4ADD(t2, t3); F4ADD(t0, t2);
            red_add_v4(&g_sums[(size_t)cls * FEAT_DIM + tid * 4], t0);
        }
        __syncthreads();
        pos = segend;
    }
}

// ---------------------------------------------------------------------------
// K3: finalize — mean + EMA + output (64000 float4s).
// ---------------------------------------------------------------------------
__global__ void __launch_bounds__(256)
finalize_kernel(const float* __restrict__ centers, float* __restrict__ out) {
    int i = blockIdx.x * blockDim.x + threadIdx.x;      // float4 index
    if (i >= NUM_CLASSES * FEAT_DIM / 4) return;
    int cls = i >> 6;
    int n = g_counts[cls];
    float4 c = reinterpret_cast<const float4*>(centers)[i];
    float4 o = c;
    if (n > 0) {
        float4 t = reinterpret_cast<const float4*>(g_sums)[i];
        float scale = ALPHA / (float)n;
        o.x = (1.0f - ALPHA) * c.x + scale * t.x;
        o.y = (1.0f - ALPHA) * c.y + scale * t.y;
        o.z = (1.0f - ALPHA) * c.z + scale * t.z;
        o.w = (1.0f - ALPHA) * c.w + scale * t.w;
    }
    reinterpret_cast<float4*>(out)[i] = o;
}

// ---------------------------------------------------------------------------
// Launch: features f32 [N,256], labels i32 [N], centers f32 [1000,256].
// ---------------------------------------------------------------------------
extern "C" void kernel_launch(void* const* d_in, const int* in_sizes, int n_in,
                              void* d_out, int out_size) {
    const float* features = (const float*)d_in[0];
    const int* labels     = (const int*)d_in[1];
    const float* centers  = (const float*)d_in[2];
    float* out            = (float*)d_out;

    index_kernel<<<HB, 256>>>(labels);
    chunksum_kernel<<<NCHUNK, 256>>>(features);
    finalize_kernel<<<(NUM_CLASSES * FEAT_DIM / 4 + 255) / 256, 256>>>(centers, out);
}